// round 14
// baseline (speedup 1.0000x reference)
#include <cuda_runtime.h>
#include <cstdint>
#include <math.h>

#define H      768
#define TT     4
#define NB     64
#define S1     513
#define S      512
#define NBB    4          // batches per scan block

// Output layout (float32), reference tuple order:
// isqa_pred(64) | crf_pred(64*512) | isqa_loss(1) | crf_loss(1) | tags(64*512) | IsQA(64)
#define OUT_ISQA_PRED 0
#define OUT_CRF_PRED  64
#define OUT_ISQA_LOSS 32832
#define OUT_CRF_LOSS  32833
#define OUT_TAGS      32834
#define OUT_ISQA      65602

typedef unsigned long long ull;

// Static device scratch (no allocation allowed)
__device__ float    g_feats[NB * S * TT];   // (b, t, state), float4 per (b,t)
__device__ float    g_isqa_logits[NB * 2];
__device__ float    g_accCrf, g_accIsqa;
__device__ unsigned g_cnt;

// ---- packed f32x2 helpers (sm_103a) ----
__device__ __forceinline__ ull f2_pack(float x, float y) {
    ull r; asm("mov.b64 %0, {%1, %2};" : "=l"(r) : "f"(x), "f"(y)); return r;
}
__device__ __forceinline__ ull f2_bcast(float x) {
    ull r; asm("mov.b64 %0, {%1, %1};" : "=l"(r) : "f"(x)); return r;
}
__device__ __forceinline__ float2 f2_get(ull v) {
    float2 r; asm("mov.b64 {%0, %1}, %2;" : "=f"(r.x), "=f"(r.y) : "l"(v)); return r;
}
__device__ __forceinline__ ull f2_add(ull a, ull b) {
    ull d; asm("add.rn.f32x2 %0, %1, %2;" : "=l"(d) : "l"(a), "l"(b)); return d;
}
__device__ __forceinline__ ull f2_mul(ull a, ull b) {
    ull d; asm("mul.rn.f32x2 %0, %1, %2;" : "=l"(d) : "l"(a), "l"(b)); return d;
}
__device__ __forceinline__ ull f2_fma(ull a, ull b, ull c) {
    ull d; asm("fma.rn.f32x2 %0, %1, %2, %3;" : "=l"(d) : "l"(a), "l"(b), "l"(c)); return d;
}

// ---------------------------------------------------------------------------
// Kernel A: 4 rows per warp sharing weight loads; 16-value butterfly
// reduction; dedicated CLS blocks. (unchanged from R12)
// ---------------------------------------------------------------------------
#define FEAT_MAIN_BLOCKS 512
#define FEAT_BLOCKS      520

__global__ void __launch_bounds__(256) featsKernel(
    const float* __restrict__ emb,
    const float* __restrict__ fc2W, const float* __restrict__ fc2b,
    const float* __restrict__ crfW, const float* __restrict__ crfb)
{
    if (blockIdx.x == 0 && threadIdx.x == 0) {
        g_cnt = 0u; g_accCrf = 0.f; g_accIsqa = 0.f;
    }

    __shared__ float Wsh[6 * H];   // rows 0-3 crf_W, 4-5 fc2_W
    __shared__ float bsh[8];
    for (int i = threadIdx.x; i < 6 * H; i += 256) {
        Wsh[i] = (i < 4 * H) ? crfW[i] : fc2W[i - 4 * H];
    }
    if (threadIdx.x < 8) {
        int r = threadIdx.x;
        bsh[r] = (r < 4) ? crfb[r] : ((r < 6) ? fc2b[r - 4] : 0.f);
    }
    __syncthreads();

    int warp = threadIdx.x >> 5, lane = threadIdx.x & 31;
    const float4* W4 = (const float4*)Wsh;       // 192 float4 per row
    const float4* E4 = (const float4*)emb;

    if (blockIdx.x < FEAT_MAIN_BLOCKS) {
        for (int g = blockIdx.x * 8 + warp; g < 8192; g += FEAT_MAIN_BLOCKS * 8) {
            int b = g >> 7, k = g & 127;
            int s0 = 1 + 4 * k;
            const float4* e0p = E4 + (size_t)(b * S1 + s0 + 0) * 192;
            const float4* e1p = E4 + (size_t)(b * S1 + s0 + 1) * 192;
            const float4* e2p = E4 + (size_t)(b * S1 + s0 + 2) * 192;
            const float4* e3p = E4 + (size_t)(b * S1 + s0 + 3) * 192;

            float a[16];
            #pragma unroll
            for (int q = 0; q < 16; q++) a[q] = 0.f;

            #pragma unroll 2
            for (int i = 0; i < 6; i++) {
                int idx = lane + 32 * i;
                float4 e0 = e0p[idx], e1 = e1p[idx], e2 = e2p[idx], e3 = e3p[idx];
                float4 w0 = W4[idx], w1 = W4[192 + idx];
                float4 w2 = W4[384 + idx], w3 = W4[576 + idx];
#define DOT4(E, W) ((E).x*(W).x + (E).y*(W).y + (E).z*(W).z + (E).w*(W).w)
                a[0]  += DOT4(e0, w0); a[1]  += DOT4(e0, w1);
                a[2]  += DOT4(e0, w2); a[3]  += DOT4(e0, w3);
                a[4]  += DOT4(e1, w0); a[5]  += DOT4(e1, w1);
                a[6]  += DOT4(e1, w2); a[7]  += DOT4(e1, w3);
                a[8]  += DOT4(e2, w0); a[9]  += DOT4(e2, w1);
                a[10] += DOT4(e2, w2); a[11] += DOT4(e2, w3);
                a[12] += DOT4(e3, w0); a[13] += DOT4(e3, w1);
                a[14] += DOT4(e3, w2); a[15] += DOT4(e3, w3);
#undef DOT4
            }

            #pragma unroll
            for (int q = 0; q < 8; q++) {
                float snd = (lane & 16) ? a[q] : a[q + 8];
                float rcv = __shfl_xor_sync(0xffffffffu, snd, 16);
                a[q] = ((lane & 16) ? a[q + 8] : a[q]) + rcv;
            }
            #pragma unroll
            for (int q = 0; q < 4; q++) {
                float snd = (lane & 8) ? a[q] : a[q + 4];
                float rcv = __shfl_xor_sync(0xffffffffu, snd, 8);
                a[q] = ((lane & 8) ? a[q + 4] : a[q]) + rcv;
            }
            #pragma unroll
            for (int q = 0; q < 2; q++) {
                float snd = (lane & 4) ? a[q] : a[q + 2];
                float rcv = __shfl_xor_sync(0xffffffffu, snd, 4);
                a[q] = ((lane & 4) ? a[q + 2] : a[q]) + rcv;
            }
            {
                float snd = (lane & 2) ? a[0] : a[1];
                float rcv = __shfl_xor_sync(0xffffffffu, snd, 2);
                a[0] = ((lane & 2) ? a[1] : a[0]) + rcv;
            }
            a[0] += __shfl_xor_sync(0xffffffffu, a[0], 1);

            int kout = (lane >> 1) & 15;
            int r = kout >> 2, j = kout & 3;
            if ((lane & 1) == 0) {
                g_feats[((size_t)b * S + (s0 - 1 + r)) * TT + j] = a[0] + bsh[j];
            }
        }
    } else {
        int c = (blockIdx.x - FEAT_MAIN_BLOCKS) * 8 + warp;   // 0..63
        const float4* e = E4 + (size_t)(c * S1) * 192;
        float p0 = 0.f, p1 = 0.f;
        #pragma unroll
        for (int i = 0; i < 6; i++) {
            int idx = lane + 32 * i;
            float4 v = e[idx];
            float4 w4 = W4[768 + idx], w5 = W4[960 + idx];
            p0 += v.x * w4.x + v.y * w4.y + v.z * w4.z + v.w * w4.w;
            p1 += v.x * w5.x + v.y * w5.y + v.z * w5.z + v.w * w5.w;
        }
        #pragma unroll
        for (int off = 16; off; off >>= 1) {
            p0 += __shfl_xor_sync(0xffffffffu, p0, off);
            p1 += __shfl_xor_sync(0xffffffffu, p1, off);
        }
        if (lane == 0) {
            g_isqa_logits[c * 2 + 0] = p0 + bsh[4];
            g_isqa_logits[c * 2 + 1] = p1 + bsh[5];
        }
    }
}

// ---------------------------------------------------------------------------
// Kernel B: 32 blocks x 256 threads, 4 batches per block.
//   blocks 0-15  (viterbi role): sequential Viterbi with NO per-step store —
//     only 32 chunk-boundary deltas go to smem. The bp phase replays each
//     chunk's deltas bit-exactly from the exact boundary (FADD is a single RN
//     op; max is exact under any association), recomputing backpointers with
//     the reference's first-max-index comparison order.
//   blocks 16-31 (forward role): linear-domain log-partition (packed f32x2,
//     power-of-2 renorm) -> Z; CLS/isqa head + losses. (unchanged)
// ---------------------------------------------------------------------------
#define SCAN_SMEM ((2048 + 512) * 16)   // FL 32KB + PRED 8KB

__global__ void __launch_bounds__(256, 1) scanKernel(
    const float* __restrict__ trans,
    const int*   __restrict__ asl,
    const int*   __restrict__ isqa_in,
    float* __restrict__ out)
{
    extern __shared__ float4 sm4[];
    float4* FL    = sm4;                 // log feats (viterbi) / exp feats (fwd)
    float4* PRED4 = sm4 + 2048;
    float*  PRED  = (float*)PRED4;
    __shared__ float4   DDb[32 * NBB];         // boundary deltas, t = 16w+15
    __shared__ float    aux[8];
    __shared__ unsigned PATHS[NBB * 32 * 4];   // [bb][chunk][entry] packed path
    __shared__ int      ESEL[NBB * 32];        // chosen entry per chunk

    int tid  = threadIdx.x;
    int warp = tid >> 5, lane = tid & 31;
    bool isFwd = blockIdx.x >= 16;
    int bb0 = (blockIdx.x & 15) * NBB;
    const float4* gf = (const float4*)g_feats + (size_t)bb0 * S;

    // ---------------- staging ----------------
    if (!isFwd) {
        for (int v = tid; v < NBB * S; v += 256) {
            int bbv = v >> 9, t = v & 511;
            FL[t * NBB + bbv] = gf[bbv * S + t];
        }
    } else {
        for (int v = tid; v < NBB * S; v += 256) {
            int bbv = v >> 9, t = v & 511;
            float4 f = gf[bbv * S + t];
            FL[t * NBB + bbv] = make_float4(__expf(f.x), __expf(f.y),
                                            __expf(f.z), __expf(f.w));
        }
    }
    __syncthreads();

    if (!isFwd) {
        // ============== VITERBI ROLE ==============
        if (warp == 0 && lane < NBB) {
            int bb = lane;
            // packed transition columns: T01[j]=(t0j,t1j), T23[j]=(t2j,t3j)
            ull T01_0 = f2_pack(trans[0], trans[4]);
            ull T01_1 = f2_pack(trans[1], trans[5]);
            ull T01_2 = f2_pack(trans[2], trans[6]);
            ull T01_3 = f2_pack(trans[3], trans[7]);
            ull T23_0 = f2_pack(trans[8],  trans[12]);
            ull T23_1 = f2_pack(trans[9],  trans[13]);
            ull T23_2 = f2_pack(trans[10], trans[14]);
            ull T23_3 = f2_pack(trans[11], trans[15]);

            float4 f0 = FL[bb];
            ull D01 = f2_pack(f0.x + trans[8],  f0.y + trans[9]);   // START=2
            ull D23 = f2_pack(f0.z + trans[10], f0.w + trans[11]);
#define VSTEP(FV)                                                             \
            {                                                                 \
                float2 p0 = f2_get(f2_add(D01, T01_0));                       \
                float2 q0 = f2_get(f2_add(D23, T23_0));                       \
                float2 p1 = f2_get(f2_add(D01, T01_1));                       \
                float2 q1 = f2_get(f2_add(D23, T23_1));                       \
                float2 p2 = f2_get(f2_add(D01, T01_2));                       \
                float2 q2 = f2_get(f2_add(D23, T23_2));                       \
                float2 p3 = f2_get(f2_add(D01, T01_3));                       \
                float2 q3 = f2_get(f2_add(D23, T23_3));                       \
                float n0 = fmaxf(fmaxf(p0.x, p0.y), fmaxf(q0.x, q0.y)) + (FV).x; \
                float n1 = fmaxf(fmaxf(p1.x, p1.y), fmaxf(q1.x, q1.y)) + (FV).y; \
                float n2 = fmaxf(fmaxf(p2.x, p2.y), fmaxf(q2.x, q2.y)) + (FV).z; \
                float n3 = fmaxf(fmaxf(p3.x, p3.y), fmaxf(q3.x, q3.y)) + (FV).w; \
                D01 = f2_pack(n0, n1); D23 = f2_pack(n2, n3);                 \
            }
#define DSTORE(W)                                                             \
            {                                                                 \
                float2 a = f2_get(D01), b2 = f2_get(D23);                     \
                DDb[(W) * NBB + bb] = make_float4(a.x, a.y, b2.x, b2.y);      \
            }
            float4 fc = FL[NBB + bb];                  // prefetch t=1
            // chunk 0: t = 1..15
            #pragma unroll
            for (int k = 1; k <= 15; ++k) {
                float4 f = fc;
                fc = FL[(k + 1) * NBB + bb];
                VSTEP(f);
            }
            DSTORE(0);
            // chunks 1..31: t = 16w .. 16w+15
            for (int w = 1; w < 32; ++w) {
                int base = w * 16;
                #pragma unroll
                for (int k = 0; k < 16; ++k) {
                    float4 f = fc;
                    int tn = base + k + 1;
                    if (tn < S) fc = FL[tn * NBB + bb];
                    VSTEP(f);
                }
                DSTORE(w);
            }
#undef VSTEP
#undef DSTORE
        } else if (warp >= 1 && warp <= NBB) {
            // gold score + tags for batch (warp-1), concurrent with seq warp
            int bb = warp - 1, b = bb0 + bb;
            const int* tg = asl + b * S1 + 1;
            float acc = 0.f;
            for (int t = lane; t < S; t += 32) {
                int tag = tg[t];
                acc += ((const float*)&FL[t * NBB + bb])[tag];
                out[OUT_TAGS + b * S + t] = (float)tag;
                if (t < S - 1) acc += trans[tag * TT + tg[t + 1]];
            }
            #pragma unroll
            for (int off = 16; off; off >>= 1)
                acc += __shfl_down_sync(0xffffffffu, acc, off);
            if (lane == 0)
                aux[bb] = acc + trans[2 * TT + tg[0]]
                              + trans[tg[S - 1] * TT + 3];
        }
        __syncthreads();

        // ---- chunk replay from exact boundary deltas: values + bps ----
        if (tid < 128) {
            int w = tid >> 2, bb = tid & 3;
            float t00 = trans[0],  t01 = trans[1],  t02 = trans[2],  t03 = trans[3];
            float t10 = trans[4],  t11 = trans[5],  t12 = trans[6],  t13 = trans[7];
            float t20 = trans[8],  t21 = trans[9],  t22 = trans[10], t23 = trans[11];
            float t30 = trans[12], t31 = trans[13], t32 = trans[14], t33 = trans[15];
            float d0, d1, d2, d3;
            if (w == 0) {
                float4 f0 = FL[bb];
                d0 = f0.x + t20; d1 = f0.y + t21;
                d2 = f0.z + t22; d3 = f0.w + t23;
            } else {
                float4 e = DDb[(w - 1) * NBB + bb];
                d0 = e.x; d1 = e.y; d2 = e.z; d3 = e.w;
            }
            unsigned r0 = 0, r1 = 0, r2 = 0, r3 = 0;
            #pragma unroll
            for (int k = 0; k < 16; ++k) {
                int t = w * 16 + k;
                if (t == 0) continue;     // t=0 is init, no transition
                float4 f = FL[t * NBB + bb];
                float n0, n1, n2, n3;
                {
                    float v0 = d0 + t00, v1 = d1 + t10, v2 = d2 + t20, v3 = d3 + t30;
                    float best = v0; int bi = 0;
                    if (v1 > best) { best = v1; bi = 1; }
                    if (v2 > best) { best = v2; bi = 2; }
                    if (v3 > best) { best = v3; bi = 3; }
                    r0 |= (unsigned)bi << (2 * k);
                    n0 = best + f.x;
                }
                {
                    float v0 = d0 + t01, v1 = d1 + t11, v2 = d2 + t21, v3 = d3 + t31;
                    float best = v0; int bi = 0;
                    if (v1 > best) { best = v1; bi = 1; }
                    if (v2 > best) { best = v2; bi = 2; }
                    if (v3 > best) { best = v3; bi = 3; }
                    r1 |= (unsigned)bi << (2 * k);
                    n1 = best + f.y;
                }
                {
                    float v0 = d0 + t02, v1 = d1 + t12, v2 = d2 + t22, v3 = d3 + t32;
                    float best = v0; int bi = 0;
                    if (v1 > best) { best = v1; bi = 1; }
                    if (v2 > best) { best = v2; bi = 2; }
                    if (v3 > best) { best = v3; bi = 3; }
                    r2 |= (unsigned)bi << (2 * k);
                    n2 = best + f.z;
                }
                {
                    float v0 = d0 + t03, v1 = d1 + t13, v2 = d2 + t23, v3 = d3 + t33;
                    float best = v0; int bi = 0;
                    if (v1 > best) { best = v1; bi = 1; }
                    if (v2 > best) { best = v2; bi = 2; }
                    if (v3 > best) { best = v3; bi = 3; }
                    r3 |= (unsigned)bi << (2 * k);
                    n3 = best + f.w;
                }
                d0 = n0; d1 = n1; d2 = n2; d3 = n3;
            }
            // decode all 4 possible entry states through this chunk
            #pragma unroll
            for (int e = 0; e < 4; ++e) {
                int cur = e; unsigned path = 0;
                #pragma unroll
                for (int k = 15; k >= 0; --k) {
                    unsigned word = (cur == 0) ? r0 : (cur == 1) ? r1
                                  : (cur == 2) ? r2 : r3;
                    cur = (int)((word >> (2 * k)) & 3u);
                    path |= (unsigned)cur << (2 * k);
                }
                PATHS[(bb * 32 + w) * 4 + e] = path;
            }
        }
        __syncthreads();

        // ---- chunk-chain: pick entry state per chunk (one thread/batch) ----
        if (tid < NBB) {
            int bb = tid;
            float4 dl = DDb[31 * NBB + bb];    // delta at t = 511
            float s0 = dl.x + trans[3],  s1 = dl.y + trans[7];
            float s2 = dl.z + trans[11], s3 = dl.w + trans[15];
            float best = s0; int cur = 0;
            if (s1 > best) { best = s1; cur = 1; }
            if (s2 > best) { best = s2; cur = 2; }
            if (s3 > best) { best = s3; cur = 3; }
            PRED[bb * S + S - 1] = (float)cur;
            for (int w = 31; w >= 0; --w) {
                ESEL[bb * 32 + w] = cur;
                cur = (int)(PATHS[(bb * 32 + w) * 4 + cur] & 3u);
            }
        }
        __syncthreads();

        // ---- parallel path writeout into PRED smem ----
        if (tid < 128) {
            int w = tid >> 2, bb = tid & 3;
            int e = ESEL[bb * 32 + w];
            unsigned path = PATHS[(bb * 32 + w) * 4 + e];
            #pragma unroll
            for (int k = 15; k >= 0; --k) {
                int t = w * 16 + k;
                if (t == 0) continue;
                PRED[bb * S + t - 1] = (float)((path >> (2 * k)) & 3u);
            }
        }
        __syncthreads();

        // ---- coalesced pred writeout ----
        for (int v = tid; v < NBB * (S / 4); v += 256) {
            int bbv = v >> 7, idx = v & 127;
            ((float4*)(out + OUT_CRF_PRED + (size_t)(bb0 + bbv) * S))[idx]
                = PRED4[bbv * (S / 4) + idx];
        }

        // ---- gold accumulation + finalize ----
        if (tid == 0) {
            float gsum = aux[0] + aux[1] + aux[2] + aux[3];
            atomicAdd(&g_accCrf, -gsum);
            __threadfence();
            unsigned old = atomicAdd(&g_cnt, 1u);
            if (old == 31u) {
                __threadfence();
                out[OUT_CRF_LOSS]  = (*(volatile float*)&g_accCrf)  * (1.f / 64.f);
                out[OUT_ISQA_LOSS] = (*(volatile float*)&g_accIsqa) * (1.f / 64.f);
            }
        }
    } else {
        // ============== FORWARD ROLE ==============
        if (warp == 0 && lane < NBB) {
            int bb = lane;
            ull EA01_0 = f2_pack(__expf(trans[0]),  __expf(trans[1]));
            ull EA23_0 = f2_pack(__expf(trans[2]),  __expf(trans[3]));
            ull EA01_1 = f2_pack(__expf(trans[4]),  __expf(trans[5]));
            ull EA23_1 = f2_pack(__expf(trans[6]),  __expf(trans[7]));
            ull EA01_2 = f2_pack(__expf(trans[8]),  __expf(trans[9]));
            ull EA23_2 = f2_pack(__expf(trans[10]), __expf(trans[11]));
            ull EA01_3 = f2_pack(__expf(trans[12]), __expf(trans[13]));
            ull EA23_3 = f2_pack(__expf(trans[14]), __expf(trans[15]));
            float P0 = __expf(trans[3]),  P1 = __expf(trans[7]);
            float P2 = __expf(trans[11]), P3 = __expf(trans[15]);

            float4 f0 = FL[bb];
            ull S01 = f2_pack(f0.x * __expf(trans[8]),  f0.y * __expf(trans[9]));
            ull S23 = f2_pack(f0.z * __expf(trans[10]), f0.w * __expf(trans[11]));
            int eAcc = 0;
#define FSTEP(EF)                                                             \
            {                                                                 \
                float2 s01 = f2_get(S01), s23 = f2_get(S23);                  \
                ull B0 = f2_bcast(s01.x), B1 = f2_bcast(s01.y);               \
                ull B2 = f2_bcast(s23.x), B3 = f2_bcast(s23.y);               \
                ull N01 = f2_mul(B0, EA01_0);                                 \
                N01 = f2_fma(B1, EA01_1, N01);                                \
                N01 = f2_fma(B2, EA01_2, N01);                                \
                N01 = f2_fma(B3, EA01_3, N01);                                \
                ull N23 = f2_mul(B0, EA23_0);                                 \
                N23 = f2_fma(B1, EA23_1, N23);                                \
                N23 = f2_fma(B2, EA23_2, N23);                                \
                N23 = f2_fma(B3, EA23_3, N23);                                \
                S01 = f2_mul(N01, f2_pack((EF).x, (EF).y));                   \
                S23 = f2_mul(N23, f2_pack((EF).z, (EF).w));                   \
            }
            int t = 1;
            float4 fc = FL[NBB + bb];                  // prefetch t=1
            for (int w = 0; w < 63; ++w) {
                #pragma unroll
                for (int k = 0; k < 8; ++k, ++t) {
                    float4 ef = fc;
                    fc = FL[(t + 1) * NBB + bb];
                    FSTEP(ef);
                }
                // exact power-of-2 renorm (all s > 0)
                float2 s01 = f2_get(S01);
                int e = (__float_as_int(s01.x) >> 23) & 255;
                eAcc += e - 127;
                ull SC = f2_bcast(__int_as_float((unsigned)(254 - e) << 23));
                S01 = f2_mul(S01, SC); S23 = f2_mul(S23, SC);
            }
            #pragma unroll
            for (int k = 0; k < 7; ++k, ++t) {         // t = 505..511
                float4 ef = fc;
                if (t < S - 1) fc = FL[(t + 1) * NBB + bb];
                FSTEP(ef);
            }
#undef FSTEP
            float2 s01 = f2_get(S01), s23 = f2_get(S23);
            float zt = (s01.x * P0 + s01.y * P1) + (s23.x * P2 + s23.y * P3);
            float Z = __logf(zt) + (float)eAcc * 0.693147180559945f;
            aux[bb] = Z;

            // CLS / isqa head for this batch
            int b = bb0 + bb;
            float l0 = g_isqa_logits[b * 2 + 0];
            float l1 = g_isqa_logits[b * 2 + 1];
            float m = fmaxf(l0, l1);
            float lse = m + __logf(__expf(l0 - m) + __expf(l1 - m));
            int y = isqa_in[b];
            aux[4 + bb] = lse - (y ? l1 : l0);
            out[OUT_ISQA_PRED + b] = (l1 > l0) ? 1.f : 0.f;
            out[OUT_ISQA + b] = (float)y;

            __syncwarp(0xFu);
            if (lane == 0) {
                atomicAdd(&g_accCrf,  aux[0] + aux[1] + aux[2] + aux[3]);
                atomicAdd(&g_accIsqa, aux[4] + aux[5] + aux[6] + aux[7]);
                __threadfence();
                unsigned old = atomicAdd(&g_cnt, 1u);
                if (old == 31u) {
                    __threadfence();
                    out[OUT_CRF_LOSS]  = (*(volatile float*)&g_accCrf)  * (1.f / 64.f);
                    out[OUT_ISQA_LOSS] = (*(volatile float*)&g_accIsqa) * (1.f / 64.f);
                }
            }
        }
    }
}

// ---------------------------------------------------------------------------
extern "C" void kernel_launch(void* const* d_in, const int* in_sizes, int n_in,
                              void* d_out, int out_size)
{
    const float* emb   = (const float*)d_in[0];
    const int*   asl   = (const int*)  d_in[1];
    const int*   isqa  = (const int*)  d_in[2];
    const float* fc2W  = (const float*)d_in[3];
    const float* fc2b  = (const float*)d_in[4];
    const float* crfW  = (const float*)d_in[5];
    const float* crfb  = (const float*)d_in[6];
    const float* trans = (const float*)d_in[7];
    float* out = (float*)d_out;

    cudaFuncSetAttribute(scanKernel,
                         cudaFuncAttributeMaxDynamicSharedMemorySize,
                         SCAN_SMEM);

    featsKernel<<<FEAT_BLOCKS, 256>>>(emb, fc2W, fc2b, crfW, crfb);
    scanKernel<<<32, 256, SCAN_SMEM>>>(trans, asl, isqa, out);
}